// round 3
// baseline (speedup 1.0000x reference)
#include <cuda_runtime.h>
#include <cuda_bf16.h>
#include <cstdint>

// Problem constants
#define NB 16           // B
#define SS 1024         // S
#define EE 8192         // E
#define DD 512          // D  (= H*DK)
#define HH 8            // H
#define DKK 64          // DK
#define LL 2            // L
#define NN (NB*SS)      // 16384 nodes
#define BEE (NB*EE)     // 131072 edges (padded)

// ---------------- scratch (device globals; no allocation allowed) -------------
__device__ float g_Q[NN*DD];
__device__ float g_K[NN*DD];
__device__ float g_V[NN*DD];
__device__ float g_AGG[NN*DD];
__device__ float g_LIN[NN*DD];
__device__ int   g_src[BEE];
__device__ int   g_tgt[BEE];
__device__ int   g_dr[BEE];
__device__ int   g_da[BEE];
__device__ int   g_rp[BEE];
__device__ float g_ev[BEE*HH];        // logit, then exp value
__device__ unsigned g_mkey[NN*HH];    // monotone-key float max
__device__ float g_denom[NN*HH];
__device__ int   g_starts[NB+1];      // g_starts[NB] = edge_total

// ---------------- monotone float<->uint key (for atomicMax on floats) ---------
__device__ __forceinline__ unsigned fkey(float f) {
    unsigned u = __float_as_uint(f);
    return (u & 0x80000000u) ? ~u : (u | 0x80000000u);
}
__device__ __forceinline__ float funkey(unsigned k) {
    unsigned u = (k & 0x80000000u) ? (k & 0x7fffffffu) : ~k;
    return __uint_as_float(u);
}

// ---------------- prep: exclusive scan of edge_len (B=16) --------------------
__global__ void prep_kernel(const int* __restrict__ edge_len) {
    if (threadIdx.x == 0 && blockIdx.x == 0) {
        int s = 0;
        for (int b = 0; b < NB; b++) { g_starts[b] = s; s += edge_len[b]; }
        g_starts[NB] = s;
    }
}

// ---------------- flatten ragged edges ---------------------------------------
__global__ void flatten_kernel(const int* __restrict__ edge_len,
                               const int* __restrict__ edge_index,
                               const int* __restrict__ drl,
                               const int* __restrict__ dac,
                               const int* __restrict__ rpp) {
    int i = blockIdx.x * blockDim.x + threadIdx.x;
    if (i >= NB*EE) return;
    int b = i / EE, e = i % EE;
    if (e < edge_len[b]) {
        int fp = g_starts[b] + e;
        g_src[fp] = edge_index[(size_t)i*2 + 0] + b*SS;
        g_tgt[fp] = edge_index[(size_t)i*2 + 1] + b*SS;
        g_dr[fp]  = drl[i];
        g_da[fp]  = dac[i];
        g_rp[fp]  = rpp[i];
    }
}

// ---------------- zero fill --------------------------------------------------
__global__ void zero_f(float* __restrict__ p, int n) {
    int i = blockIdx.x * blockDim.x + threadIdx.x;
    if (i < n) p[i] = 0.f;
}

__global__ void layer_init() {
    int i = blockIdx.x * blockDim.x + threadIdx.x;
    if (i < NN*DD) g_AGG[i] = 0.f;
    if (i < NN*HH) { g_mkey[i] = 0u; g_denom[i] = 0.f; }
}

// ---------------- SGEMM core: C[128,128 tile] = A[M,512] @ B[512,512] --------
// 128x128 block tile, BK=16, 256 threads, 8x8 microtile.
// Software-pipelined: register-staged global loads overlap FFMA on current
// smem tile; double-buffered smem, one __syncthreads per k-tile.
template <bool RES>
__device__ __forceinline__ void sgemm_body(const float* __restrict__ A,
                                           const float* __restrict__ B,
                                           float* __restrict__ C,
                                           const float* __restrict__ res,
                                           int bx, int by) {
    __shared__ float As[2][16][128];
    __shared__ float Bs[2][16][128];
    const int tid = threadIdx.x;
    const int tx = tid & 15;          // 0..15 (N direction)
    const int ty = tid >> 4;          // 0..15 (M direction)

    // Per-thread global-load coordinates (fixed across tiles)
    const int a_m0  = tid >> 2;               // rows for the 2 A-fragments
    const int a_m1  = (tid + 256) >> 2;
    const int a_kq  = (tid & 3) * 4;          // k offset within tile
    const int b_k0  = tid >> 5;               // k rows for the 2 B-fragments
    const int b_k1  = (tid + 256) >> 5;
    const int b_nq  = (tid & 31) * 4;         // n offset

    float acc[8][8];
    #pragma unroll
    for (int i = 0; i < 8; i++)
        #pragma unroll
        for (int j = 0; j < 8; j++) acc[i][j] = 0.f;

    const float* Aptr = A + (size_t)by * 128 * 512;
    const float* Bptr = B + bx * 128;

    float4 ra0, ra1, rb0, rb1;
    auto fetch = [&](int kt) {
        ra0 = *(const float4*)(Aptr + (size_t)a_m0 * 512 + kt + a_kq);
        ra1 = *(const float4*)(Aptr + (size_t)a_m1 * 512 + kt + a_kq);
        rb0 = *(const float4*)(Bptr + (size_t)(kt + b_k0) * 512 + b_nq);
        rb1 = *(const float4*)(Bptr + (size_t)(kt + b_k1) * 512 + b_nq);
    };
    auto stage = [&](int buf) {
        As[buf][a_kq+0][a_m0] = ra0.x; As[buf][a_kq+1][a_m0] = ra0.y;
        As[buf][a_kq+2][a_m0] = ra0.z; As[buf][a_kq+3][a_m0] = ra0.w;
        As[buf][a_kq+0][a_m1] = ra1.x; As[buf][a_kq+1][a_m1] = ra1.y;
        As[buf][a_kq+2][a_m1] = ra1.z; As[buf][a_kq+3][a_m1] = ra1.w;
        *(float4*)&Bs[buf][b_k0][b_nq] = rb0;
        *(float4*)&Bs[buf][b_k1][b_nq] = rb1;
    };

    fetch(0);
    stage(0);
    __syncthreads();

    for (int kt = 0; kt < 512; kt += 16) {
        const int cur = (kt >> 4) & 1;
        const bool more = (kt + 16) < 512;
        if (more) fetch(kt + 16);            // non-blocking LDGs overlap compute

        #pragma unroll
        for (int k = 0; k < 16; k++) {
            float4 a0 = *(const float4*)&As[cur][k][ty*8];
            float4 a1 = *(const float4*)&As[cur][k][ty*8+4];
            float4 b0 = *(const float4*)&Bs[cur][k][tx*8];
            float4 b1 = *(const float4*)&Bs[cur][k][tx*8+4];
            float a[8] = {a0.x,a0.y,a0.z,a0.w,a1.x,a1.y,a1.z,a1.w};
            float b[8] = {b0.x,b0.y,b0.z,b0.w,b1.x,b1.y,b1.z,b1.w};
            #pragma unroll
            for (int i = 0; i < 8; i++)
                #pragma unroll
                for (int j = 0; j < 8; j++) acc[i][j] += a[i] * b[j];
        }

        if (more) stage(cur ^ 1);            // prev buffer fully consumed (sync'd last iter)
        __syncthreads();
    }

    const int mbase = by*128 + ty*8;
    const int nbase = bx*128 + tx*8;
    #pragma unroll
    for (int i = 0; i < 8; i++) {
        float* crow = C + (size_t)(mbase + i) * 512 + nbase;
        #pragma unroll
        for (int j = 0; j < 8; j += 4) {
            float4 v = make_float4(acc[i][j], acc[i][j+1], acc[i][j+2], acc[i][j+3]);
            if (RES) {
                const float4 rv = *(const float4*)(res + (size_t)(mbase + i) * 512 + nbase + j);
                v.x += rv.x; v.y += rv.y; v.z += rv.z; v.w += rv.w;
            }
            *(float4*)(crow + j) = v;
        }
    }
}

// Fused Q/K/V projection: blockIdx.z selects the weight/output pair.
__global__ void __launch_bounds__(256, 2)
qkv_gemm(const float* __restrict__ A,
         const float* __restrict__ Bq, const float* __restrict__ Bk,
         const float* __restrict__ Bv,
         float* __restrict__ Cq, float* __restrict__ Ck, float* __restrict__ Cv) {
    const float* B = (blockIdx.z == 0) ? Bq : (blockIdx.z == 1) ? Bk : Bv;
    float*       C = (blockIdx.z == 0) ? Cq : (blockIdx.z == 1) ? Ck : Cv;
    sgemm_body<false>(A, B, C, nullptr, blockIdx.x, blockIdx.y);
}

// Output projection with fused residual add.
__global__ void __launch_bounds__(256, 2)
o_gemm(const float* __restrict__ A, const float* __restrict__ B,
       float* __restrict__ C, const float* __restrict__ res) {
    sgemm_body<true>(A, B, C, res, blockIdx.x, blockIdx.y);
}

// ---------------- edge pass 1: logits + segment max --------------------------
// one warp per valid edge
__global__ void edge_logits(const float* __restrict__ dre,
                            const float* __restrict__ dae,
                            const float* __restrict__ rpe) {
    int warp = (blockIdx.x * blockDim.x + threadIdx.x) >> 5;
    int lane = threadIdx.x & 31;
    int total = g_starts[NB];
    if (warp >= total) return;
    int e = warp;
    int src = g_src[e], tgt = g_tgt[e];
    int d0 = lane * 2;
    int dr = g_dr[e], da = g_da[e], rp = g_rp[e];
    const float2 drv = *(const float2*)(dre + dr*DKK + d0);
    const float2 dav = *(const float2*)(dae + da*DKK + d0);
    const float2 rpv = *(const float2*)(rpe + rp*DKK + d0);
    float r0 = drv.x + dav.x + rpv.x;
    float r1 = drv.y + dav.y + rpv.y;
    #pragma unroll
    for (int h = 0; h < HH; h++) {
        const float2 kk = *(const float2*)(g_K + (size_t)src*DD + h*DKK + d0);
        const float2 qq = *(const float2*)(g_Q + (size_t)tgt*DD + h*DKK + d0);
        float p = qq.x * (kk.x + r0) + qq.y * (kk.y + r1);
        #pragma unroll
        for (int off = 16; off; off >>= 1) p += __shfl_xor_sync(0xffffffffu, p, off);
        if (lane == 0) {
            float lg = p * 0.125f;     // 1/sqrt(64)
            g_ev[(size_t)e*HH + h] = lg;
            atomicMax(&g_mkey[tgt*HH + h], fkey(lg));
        }
    }
}

// ---------------- edge pass 2: exp + segment sum -----------------------------
__global__ void edge_expsum() {
    int idx = blockIdx.x * blockDim.x + threadIdx.x;
    int total = g_starts[NB];
    if (idx >= total * HH) return;
    int e = idx >> 3;
    int h = idx & 7;
    int tgt = g_tgt[e];
    float m = funkey(g_mkey[tgt*HH + h]);
    float ev = __expf(g_ev[idx] - m);
    g_ev[idx] = ev;
    atomicAdd(&g_denom[tgt*HH + h], ev);
}

// ---------------- edge pass 3: alpha + scatter aggregation -------------------
// one warp per valid edge
__global__ void edge_aggregate(const float* __restrict__ dre,
                               const float* __restrict__ dae,
                               const float* __restrict__ rpe,
                               float* __restrict__ alpha_out) {
    int warp = (blockIdx.x * blockDim.x + threadIdx.x) >> 5;
    int lane = threadIdx.x & 31;
    int total = g_starts[NB];
    if (warp >= total) return;
    int e = warp;
    int src = g_src[e], tgt = g_tgt[e];
    int d0 = lane * 2;
    int dr = g_dr[e], da = g_da[e], rp = g_rp[e];
    const float2 drv = *(const float2*)(dre + dr*DKK + d0);
    const float2 dav = *(const float2*)(dae + da*DKK + d0);
    const float2 rpv = *(const float2*)(rpe + rp*DKK + d0);
    float r0 = drv.x + dav.x + rpv.x;
    float r1 = drv.y + dav.y + rpv.y;

    float al[HH];
    #pragma unroll
    for (int h = 0; h < HH; h++)
        al[h] = g_ev[(size_t)e*HH + h] / (g_denom[tgt*HH + h] + 1e-9f);
    if (lane < HH) alpha_out[(size_t)e*HH + lane] = al[lane];

    #pragma unroll
    for (int h = 0; h < HH; h++) {
        const float2 vv = *(const float2*)(g_V + (size_t)src*DD + h*DKK + d0);
        atomicAdd(&g_AGG[(size_t)tgt*DD + h*DKK + d0],     al[h] * (vv.x + r0));
        atomicAdd(&g_AGG[(size_t)tgt*DD + h*DKK + d0 + 1], al[h] * (vv.y + r1));
    }
}

// ---------------- LayerNorm (+ residual already fused in GEMM) ---------------
__global__ void ln_kernel(const float* __restrict__ x,
                          const float* __restrict__ scale,
                          const float* __restrict__ bias,
                          float* __restrict__ out, int do_relu) {
    int row = blockIdx.x;
    const float* xr = x + (size_t)row * DD;
    int t = threadIdx.x;               // 128 threads, 4 elems each
    float v[4];
    float s = 0.f;
    #pragma unroll
    for (int i = 0; i < 4; i++) { v[i] = xr[t + i*128]; s += v[i]; }
    __shared__ float red[4];
    #pragma unroll
    for (int off = 16; off; off >>= 1) s += __shfl_xor_sync(0xffffffffu, s, off);
    if ((t & 31) == 0) red[t >> 5] = s;
    __syncthreads();
    s = red[0] + red[1] + red[2] + red[3];
    float mu = s * (1.f / DD);
    float vs = 0.f;
    #pragma unroll
    for (int i = 0; i < 4; i++) { float d = v[i] - mu; vs += d*d; }
    __syncthreads();
    #pragma unroll
    for (int off = 16; off; off >>= 1) vs += __shfl_xor_sync(0xffffffffu, vs, off);
    if ((t & 31) == 0) red[t >> 5] = vs;
    __syncthreads();
    vs = red[0] + red[1] + red[2] + red[3];
    float rstd = rsqrtf(vs * (1.f / DD) + 1e-5f);
    float* orow = out + (size_t)row * DD;
    #pragma unroll
    for (int i = 0; i < 4; i++) {
        int d = t + i*128;
        float y = (v[i] - mu) * rstd * scale[d] + bias[d];
        if (do_relu) y = fmaxf(y, 0.f);
        orow[d] = y;
    }
}

// ---------------- host orchestration -----------------------------------------
extern "C" void kernel_launch(void* const* d_in, const int* in_sizes, int n_in,
                              void* d_out, int out_size) {
    const float* inp        = (const float*)d_in[0];
    const int*   edge_len   = (const int*)  d_in[2];
    const int*   edge_index = (const int*)  d_in[3];
    const int*   rp_in      = (const int*)  d_in[4];   // dep_rel_pos_edge_rep
    const int*   dr_in      = (const int*)  d_in[6];   // deprel_edge_rep
    const int*   da_in      = (const int*)  d_in[7];   // deparc_edge_rep
    const float* Wq         = (const float*)d_in[14];
    const float* Wk         = (const float*)d_in[15];
    const float* Wv         = (const float*)d_in[16];
    const float* Wo         = (const float*)d_in[17];
    const float* dre        = (const float*)d_in[18];
    const float* dae        = (const float*)d_in[19];
    const float* rpe        = (const float*)d_in[20];
    const float* ln_s       = (const float*)d_in[21];
    const float* ln_b       = (const float*)d_in[22];

    float* out   = (float*)d_out;
    float* reps  = out;                             // [L, N, D]
    float* attns = out + (size_t)LL * NN * DD;      // [L, BE, H]

    float *Qp, *Kp, *Vp, *AGGp, *LINp;
    cudaGetSymbolAddress((void**)&Qp,   g_Q);
    cudaGetSymbolAddress((void**)&Kp,   g_K);
    cudaGetSymbolAddress((void**)&Vp,   g_V);
    cudaGetSymbolAddress((void**)&AGGp, g_AGG);
    cudaGetSymbolAddress((void**)&LINp, g_LIN);

    prep_kernel<<<1, 32>>>(edge_len);
    flatten_kernel<<<(NB*EE + 255)/256, 256>>>(edge_len, edge_index, dr_in, da_in, rp_in);
    zero_f<<<(LL*BEE*HH + 255)/256, 256>>>(attns, LL*BEE*HH);

    dim3 qkv_grid(4, 128, 3);        // N/128 x M/128 x {Q,K,V}
    dim3 gemm_grid(4, 128);
    const float* h = inp;
    for (int l = 0; l < LL; l++) {
        const size_t woff = (size_t)l * 512 * 512;
        qkv_gemm<<<qkv_grid, 256>>>(h, Wq + woff, Wk + woff, Wv + woff, Qp, Kp, Vp);

        layer_init<<<(NN*DD + 255)/256, 256>>>();

        const float* drl = dre + (size_t)l * 50 * DKK;
        const float* dal = dae + (size_t)l * 3  * DKK;
        const float* rpl = rpe + (size_t)l * 21 * DKK;

        edge_logits<<<BEE/8, 256>>>(drl, dal, rpl);
        edge_expsum<<<(BEE*HH + 255)/256, 256>>>();
        edge_aggregate<<<BEE/8, 256>>>(drl, dal, rpl, attns + (size_t)l * BEE * HH);

        o_gemm<<<gemm_grid, 256>>>(AGGp, Wo + woff, LINp, h);

        float* rep_l = reps + (size_t)l * NN * DD;
        ln_kernel<<<NN, 128>>>(LINp, ln_s + (size_t)l * DD, ln_b + (size_t)l * DD,
                               rep_l, (l < LL - 1) ? 1 : 0);
        h = rep_l;
    }
}